// round 5
// baseline (speedup 1.0000x reference)
#include <cuda_runtime.h>

// QLayerOriginal: rho <- U rho U^dagger over 16 blocks of 3 angles.
// Exact reduction: U(p0,p1,p2) = D(p1/2) R(p0/2) D(p2/2), D(f)=diag(e^{if},e^{-if}).
// On the complex Bloch vector t (rho = t0 I + t.sigma), conjugation by U is the
// real SO(3) map Rz(-p1) Ry(p0) Rz(-p2) on Re(t) and Im(t) separately; t0 invariant.
// Adjacent Rz fuse: Rz(-p2^0), { Ry(p0^k), Rz(-(p1^k+p2^{k+1})) }, final Rz(-p1^15).
//
// Output layout adapts to out_size:
//   out_size >= 8*B floats : interleaved complex64 (re,im per entry)
//   out_size >= 4*B floats : REAL PARTS only (np.real of the complex result)
// Every store is bounds-guarded by out_size — the kernel cannot write OOB.

#define NTHREADS 256

__global__ void __launch_bounds__(NTHREADS) qlayer_kernel(
    const float* __restrict__ rho_real,
    const float* __restrict__ rho_imag,
    const float* __restrict__ x,
    const float* __restrict__ w,
    const float* __restrict__ theta,
    float* __restrict__ out,
    long long nbatch,
    long long out_elems,
    int full_complex)
{
    __shared__ float s_w[48];
    __shared__ float s_t[48];
    int tid = threadIdx.x;
    if (tid < 48) {
        s_w[tid] = w ? w[tid] : 0.0f;
        s_t[tid] = theta ? theta[tid] : 0.0f;
    }
    __syncthreads();

    long long i = (long long)blockIdx.x * NTHREADS + tid;
    if (i >= nbatch) return;
    if (!rho_real || !rho_imag || !x || !out) return;

    // ---- phi = theta + w*x ----
    float phi[48];
    const float* xr = x + i * 48;
#pragma unroll
    for (int j = 0; j < 48; ++j)
        phi[j] = fmaf(xr[j], s_w[j], s_t[j]);

    // ---- load rho ----
    const float* rrp = rho_real + i * 4;
    const float* rip = rho_imag + i * 4;
    float rr0 = rrp[0], rr1 = rrp[1], rr2 = rrp[2], rr3 = rrp[3];
    float ri0 = rip[0], ri1 = rip[1], ri2 = rip[2], ri3 = rip[3];

    // ---- Pauli decomposition ----
    float t0r = 0.5f * (rr0 + rr3), t0i = 0.5f * (ri0 + ri3);
    float vzr = 0.5f * (rr0 - rr3), vzi = 0.5f * (ri0 - ri3);
    float vxr = 0.5f * (rr1 + rr2), vxi = 0.5f * (ri1 + ri2);
    float vyr = 0.5f * (ri2 - ri1), vyi = 0.5f * (rr1 - rr2);

    // ---- rotation chain: 17 Rz + 16 Ry ----
    float zpsi = -phi[2];
#pragma unroll
    for (int k = 0; k < 16; ++k) {
        float sz, cz;
        __sincosf(zpsi, &sz, &cz);
        {
            float nxr = cz * vxr - sz * vyr;
            float nyr = sz * vxr + cz * vyr;
            float nxi = cz * vxi - sz * vyi;
            float nyi = sz * vxi + cz * vyi;
            vxr = nxr; vyr = nyr; vxi = nxi; vyi = nyi;
        }
        float sy, cy;
        __sincosf(phi[3 * k], &sy, &cy);
        {
            float nxr = cy * vxr + sy * vzr;
            float nzr = -sy * vxr + cy * vzr;
            float nxi = cy * vxi + sy * vzi;
            float nzi = -sy * vxi + cy * vzi;
            vxr = nxr; vzr = nzr; vxi = nxi; vzi = nzi;
        }
        zpsi = (k < 15) ? -(phi[3 * k + 1] + phi[3 * k + 5]) : -phi[3 * k + 1];
    }
    {
        float sz, cz;
        __sincosf(zpsi, &sz, &cz);
        float nxr = cz * vxr - sz * vyr;
        float nyr = sz * vxr + cz * vyr;
        float nxi = cz * vxi - sz * vyi;
        float nyi = sz * vxi + cz * vyi;
        vxr = nxr; vyr = nyr; vxi = nxi; vyi = nyi;
    }

    // ---- reconstruct rho' ----
    // r00 = t0+tz, r01 = tx - i ty, r10 = tx + i ty, r11 = t0-tz
    float o_r00r = t0r + vzr, o_r00i = t0i + vzi;
    float o_r01r = vxr + vyi, o_r01i = vxi - vyr;
    float o_r10r = vxr - vyi, o_r10i = vxi + vyr;
    float o_r11r = t0r - vzr, o_r11i = t0i - vzi;

    if (full_complex) {
        long long base = i * 8;
        if (base + 7 < out_elems) {
            out[base + 0] = o_r00r; out[base + 1] = o_r00i;
            out[base + 2] = o_r01r; out[base + 3] = o_r01i;
            out[base + 4] = o_r10r; out[base + 5] = o_r10i;
            out[base + 6] = o_r11r; out[base + 7] = o_r11i;
        }
    } else {
        long long base = i * 4;
        if (base + 3 < out_elems) {
            out[base + 0] = o_r00r;
            out[base + 1] = o_r01r;
            out[base + 2] = o_r10r;
            out[base + 3] = o_r11r;
        }
    }
}

extern "C" void kernel_launch(void* const* d_in, const int* in_sizes, int n_in,
                              void* d_out, int out_size)
{
    const float* rho_real = nullptr;
    const float* rho_imag = nullptr;
    const float* x = nullptr;
    const float* w = nullptr;
    const float* theta = nullptr;
    long long B = 0;

    // 1) Strict metadata order (rho_real, rho_imag, x, w, theta).
    if (n_in >= 5) {
        long long s0 = in_sizes[0], s1 = in_sizes[1], s2 = in_sizes[2];
        long long s3 = in_sizes[3], s4 = in_sizes[4];
        if (s0 == s1 && s0 > 0 && (s0 % 4) == 0 &&
            s2 == 12 * s0 && s3 == 48 && s4 == 48) {
            rho_real = (const float*)d_in[0];
            rho_imag = (const float*)d_in[1];
            x        = (const float*)d_in[2];
            w        = (const float*)d_in[3];
            theta    = (const float*)d_in[4];
            B = s0 / 4;
        }
    }

    // 2) Fallback: consistency search over sizes.
    if (B == 0) {
        for (int a = 0; a < n_in && B == 0; ++a) {
            for (int b = a + 1; b < n_in && B == 0; ++b) {
                long long sa = in_sizes[a], sb = in_sizes[b];
                if (sa != sb || sa <= 0 || (sa % 4) != 0) continue;
                long long Bc = sa / 4;
                if (Bc < 2) continue;
                int xk = -1;
                for (int c = 0; c < n_in; ++c) {
                    if (c == a || c == b) continue;
                    if ((long long)in_sizes[c] == 48LL * Bc) { xk = c; break; }
                }
                if (xk < 0) continue;
                int s1i = -1, s2i = -1;
                for (int c = 0; c < n_in; ++c) {
                    if (c == a || c == b || c == xk) continue;
                    if (in_sizes[c] == 48) {
                        if (s1i < 0) s1i = c;
                        else if (s2i < 0) { s2i = c; break; }
                    }
                }
                if (s1i < 0 || s2i < 0) continue;
                rho_real = (const float*)d_in[a];
                rho_imag = (const float*)d_in[b];
                x        = (const float*)d_in[xk];
                w        = (const float*)d_in[s1i];
                theta    = (const float*)d_in[s2i];
                B = Bc;
            }
        }
    }

    float* out = (float*)d_out;
    long long out_elems = (long long)out_size;
    // Decide layout from the REAL buffer size: complex-interleaved needs 8*B floats.
    int full_complex = (B > 0 && out_elems >= 8 * B) ? 1 : 0;

    unsigned nblk = (unsigned)(B > 0 ? (B + NTHREADS - 1) / NTHREADS : 1);
    qlayer_kernel<<<nblk, NTHREADS>>>(rho_real, rho_imag, x, w, theta, out,
                                      B, out_elems, full_complex);
}

// round 6
// speedup vs baseline: 1.9719x; 1.9719x over previous
#include <cuda_runtime.h>
#include <stdint.h>

// QLayerOriginal: rho <- U rho U^dagger over 16 blocks of 3 angles.
// Exact reduction: U(p0,p1,p2) = D(p1/2) R(p0/2) D(p2/2); on the complex Bloch
// vector t (rho = t0 I + t.sigma) conjugation is the REAL SO(3) map
// Rz(-p1) Ry(p0) Rz(-p2) applied to Re(t), Im(t); t0 invariant. Adjacent Rz fuse:
//   Rz(-p2^0), { Ry(p0^k), Rz(-(p1^k+p2^{k+1})) }_{k<15}, Ry(p0^15), Rz(-p1^15).
//
// Output: adaptive — out_size >= 8B floats: interleaved complex64;
//         else (the actual dataset case): REAL PARTS only, 4 floats/sample.
// All stores bounds-guarded by out_size.

#define NTHREADS 256

// ---- shared math body ------------------------------------------------------
__device__ __forceinline__ void qlayer_compute(
    const float phi[48],
    float rr0, float rr1, float rr2, float rr3,
    float ri0, float ri1, float ri2, float ri3,
    float o[8])
{
    // Pauli decomposition
    float t0r = 0.5f * (rr0 + rr3), t0i = 0.5f * (ri0 + ri3);
    float vzr = 0.5f * (rr0 - rr3), vzi = 0.5f * (ri0 - ri3);
    float vxr = 0.5f * (rr1 + rr2), vxi = 0.5f * (ri1 + ri2);
    float vyr = 0.5f * (ri2 - ri1), vyi = 0.5f * (rr1 - rr2);

    float zpsi = -phi[2];
#pragma unroll
    for (int k = 0; k < 16; ++k) {
        float sz, cz;
        __sincosf(zpsi, &sz, &cz);
        {
            float nxr = cz * vxr - sz * vyr;
            float nyr = sz * vxr + cz * vyr;
            float nxi = cz * vxi - sz * vyi;
            float nyi = sz * vxi + cz * vyi;
            vxr = nxr; vyr = nyr; vxi = nxi; vyi = nyi;
        }
        float sy, cy;
        __sincosf(phi[3 * k], &sy, &cy);
        {
            float nxr = cy * vxr + sy * vzr;
            float nzr = -sy * vxr + cy * vzr;
            float nxi = cy * vxi + sy * vzi;
            float nzi = -sy * vxi + cy * vzi;
            vxr = nxr; vzr = nzr; vxi = nxi; vzi = nzi;
        }
        zpsi = (k < 15) ? -(phi[3 * k + 1] + phi[3 * k + 5]) : -phi[3 * k + 1];
    }
    {
        float sz, cz;
        __sincosf(zpsi, &sz, &cz);
        float nxr = cz * vxr - sz * vyr;
        float nyr = sz * vxr + cz * vyr;
        float nxi = cz * vxi - sz * vyi;
        float nyi = sz * vxi + cz * vyi;
        vxr = nxr; vyr = nyr; vxi = nxi; vyi = nyi;
    }

    // r00=t0+tz, r01=tx-i ty, r10=tx+i ty, r11=t0-tz
    o[0] = t0r + vzr; o[1] = t0i + vzi;
    o[2] = vxr + vyi; o[3] = vxi - vyr;
    o[4] = vxr - vyi; o[5] = vxi + vyr;
    o[6] = t0r - vzr; o[7] = t0i - vzi;
}

// ---- vectorized kernel (16B-aligned buffers) -------------------------------
__global__ void __launch_bounds__(NTHREADS) qlayer_kernel_vec(
    const float* __restrict__ rho_real,
    const float* __restrict__ rho_imag,
    const float* __restrict__ x,
    const float* __restrict__ w,
    const float* __restrict__ theta,
    float* __restrict__ out,
    long long nbatch,
    long long out_elems,
    int full_complex)
{
    __shared__ float s_w[48];
    __shared__ float s_t[48];
    int tid = threadIdx.x;
    if (tid < 48) {
        s_w[tid] = w[tid];
        s_t[tid] = theta[tid];
    }
    __syncthreads();

    long long i = (long long)blockIdx.x * NTHREADS + tid;
    if (i >= nbatch) return;

    float phi[48];
    const float4* xv = (const float4*)x + i * 12;
#pragma unroll
    for (int q = 0; q < 12; ++q) {
        float4 v = __ldcs(xv + q);
        phi[4 * q + 0] = fmaf(v.x, s_w[4 * q + 0], s_t[4 * q + 0]);
        phi[4 * q + 1] = fmaf(v.y, s_w[4 * q + 1], s_t[4 * q + 1]);
        phi[4 * q + 2] = fmaf(v.z, s_w[4 * q + 2], s_t[4 * q + 2]);
        phi[4 * q + 3] = fmaf(v.w, s_w[4 * q + 3], s_t[4 * q + 3]);
    }

    float4 rr = __ldcs((const float4*)rho_real + i);
    float4 ri = __ldcs((const float4*)rho_imag + i);

    float o[8];
    qlayer_compute(phi, rr.x, rr.y, rr.z, rr.w, ri.x, ri.y, ri.z, ri.w, o);

    if (full_complex) {
        long long base = i * 8;
        if (base + 7 < out_elems) {
            float4* op = (float4*)(out + base);
            __stcs(op + 0, make_float4(o[0], o[1], o[2], o[3]));
            __stcs(op + 1, make_float4(o[4], o[5], o[6], o[7]));
        }
    } else {
        long long base = i * 4;
        if (base + 3 < out_elems) {
            __stcs((float4*)(out + base), make_float4(o[0], o[2], o[4], o[6]));
        }
    }
}

// ---- scalar fallback (any alignment) ---------------------------------------
__global__ void __launch_bounds__(NTHREADS) qlayer_kernel_scalar(
    const float* __restrict__ rho_real,
    const float* __restrict__ rho_imag,
    const float* __restrict__ x,
    const float* __restrict__ w,
    const float* __restrict__ theta,
    float* __restrict__ out,
    long long nbatch,
    long long out_elems,
    int full_complex)
{
    __shared__ float s_w[48];
    __shared__ float s_t[48];
    int tid = threadIdx.x;
    if (tid < 48) {
        s_w[tid] = w[tid];
        s_t[tid] = theta[tid];
    }
    __syncthreads();

    long long i = (long long)blockIdx.x * NTHREADS + tid;
    if (i >= nbatch) return;

    float phi[48];
    const float* xr = x + i * 48;
#pragma unroll
    for (int j = 0; j < 48; ++j)
        phi[j] = fmaf(xr[j], s_w[j], s_t[j]);

    const float* rrp = rho_real + i * 4;
    const float* rip = rho_imag + i * 4;

    float o[8];
    qlayer_compute(phi, rrp[0], rrp[1], rrp[2], rrp[3],
                        rip[0], rip[1], rip[2], rip[3], o);

    if (full_complex) {
        long long base = i * 8;
        if (base + 7 < out_elems) {
#pragma unroll
            for (int j = 0; j < 8; ++j) out[base + j] = o[j];
        }
    } else {
        long long base = i * 4;
        if (base + 3 < out_elems) {
            out[base + 0] = o[0];
            out[base + 1] = o[2];
            out[base + 2] = o[4];
            out[base + 3] = o[6];
        }
    }
}

extern "C" void kernel_launch(void* const* d_in, const int* in_sizes, int n_in,
                              void* d_out, int out_size)
{
    const float* rho_real = nullptr;
    const float* rho_imag = nullptr;
    const float* x = nullptr;
    const float* w = nullptr;
    const float* theta = nullptr;
    long long B = 0;

    // 1) Strict metadata order (rho_real, rho_imag, x, w, theta).
    if (n_in >= 5) {
        long long s0 = in_sizes[0], s1 = in_sizes[1], s2 = in_sizes[2];
        long long s3 = in_sizes[3], s4 = in_sizes[4];
        if (s0 == s1 && s0 > 0 && (s0 % 4) == 0 &&
            s2 == 12 * s0 && s3 == 48 && s4 == 48) {
            rho_real = (const float*)d_in[0];
            rho_imag = (const float*)d_in[1];
            x        = (const float*)d_in[2];
            w        = (const float*)d_in[3];
            theta    = (const float*)d_in[4];
            B = s0 / 4;
        }
    }

    // 2) Fallback: consistency search over sizes.
    if (B == 0) {
        for (int a = 0; a < n_in && B == 0; ++a) {
            for (int b = a + 1; b < n_in && B == 0; ++b) {
                long long sa = in_sizes[a], sb = in_sizes[b];
                if (sa != sb || sa <= 0 || (sa % 4) != 0) continue;
                long long Bc = sa / 4;
                if (Bc < 2) continue;
                int xk = -1;
                for (int c = 0; c < n_in; ++c) {
                    if (c == a || c == b) continue;
                    if ((long long)in_sizes[c] == 48LL * Bc) { xk = c; break; }
                }
                if (xk < 0) continue;
                int s1i = -1, s2i = -1;
                for (int c = 0; c < n_in; ++c) {
                    if (c == a || c == b || c == xk) continue;
                    if (in_sizes[c] == 48) {
                        if (s1i < 0) s1i = c;
                        else if (s2i < 0) { s2i = c; break; }
                    }
                }
                if (s1i < 0 || s2i < 0) continue;
                rho_real = (const float*)d_in[a];
                rho_imag = (const float*)d_in[b];
                x        = (const float*)d_in[xk];
                w        = (const float*)d_in[s1i];
                theta    = (const float*)d_in[s2i];
                B = Bc;
            }
        }
    }

    float* out = (float*)d_out;
    long long out_elems = (long long)out_size;
    int full_complex = (B > 0 && out_elems >= 8 * B) ? 1 : 0;

    bool aligned =
        (((uintptr_t)x        & 15) == 0) &&
        (((uintptr_t)rho_real & 15) == 0) &&
        (((uintptr_t)rho_imag & 15) == 0) &&
        (((uintptr_t)out      & 15) == 0);

    unsigned nblk = (unsigned)(B > 0 ? (B + NTHREADS - 1) / NTHREADS : 1);
    if (B > 0 && aligned) {
        qlayer_kernel_vec<<<nblk, NTHREADS>>>(rho_real, rho_imag, x, w, theta, out,
                                              B, out_elems, full_complex);
    } else {
        qlayer_kernel_scalar<<<nblk, NTHREADS>>>(rho_real, rho_imag, x, w, theta, out,
                                                 B, out_elems, full_complex);
    }
}

// round 8
// speedup vs baseline: 2.2968x; 1.1647x over previous
#include <cuda_runtime.h>
#include <stdint.h>

// QLayerOriginal: rho <- U rho U^dagger over 16 blocks of 3 angles.
// Exact reduction: on the complex Bloch vector t (rho = t0 I + t.sigma),
// conjugation by U(p0,p1,p2)=D(p1/2)R(p0/2)D(p2/2) is the REAL SO(3) map
// Rz(-p1) Ry(p0) Rz(-p2) applied to Re(t), Im(t); t0 invariant.
// Loop form without lookahead (zacc carries previous block's p1):
//   zacc=0; for k: Rz(-(zacc+phi[3k+2])); Ry(phi[3k]); zacc=phi[3k+1]; end Rz(-zacc).
//
// R7: x staged through shared memory with perfectly coalesced float4 loads;
// phi computed on the fly from smem (row stride 49 -> bank-conflict-free),
// killing the 48-register phi array (occupancy up, L1 wavefronts down 8x).
//
// Output adaptive: out_size >= 8B floats -> interleaved complex64;
// else REAL PARTS only (the dataset case). All stores bounds-guarded.

#define NTHREADS 128
#define ROWS NTHREADS           // samples per block
#define RSTRIDE 49              // padded row stride in floats

__global__ void __launch_bounds__(NTHREADS) qlayer_kernel_vec(
    const float* __restrict__ rho_real,
    const float* __restrict__ rho_imag,
    const float* __restrict__ x,
    const float* __restrict__ w,
    const float* __restrict__ theta,
    float* __restrict__ out,
    long long nbatch,
    long long out_elems,
    int full_complex)
{
    __shared__ float sx[ROWS * RSTRIDE];      // 128*49*4 = 25088 B
    __shared__ float s_w[48];
    __shared__ float s_t[48];

    int tid = threadIdx.x;
    if (tid < 48) {
        s_w[tid] = w[tid];
        s_t[tid] = theta[tid];
    }

    long long blockBase = (long long)blockIdx.x * ROWS;
    long long nLocal = nbatch - blockBase;            // samples this block owns
    if (nLocal > ROWS) nLocal = ROWS;

    // ---- cooperative, fully coalesced staging of x into smem ----
    // Block slab: nLocal*48 floats = nLocal*12 float4, consecutive in gmem.
    {
        const float4* xg = (const float4*)x + blockBase * 12;
        int nv = (int)(nLocal * 12);
#pragma unroll
        for (int k = 0; k < 12; ++k) {
            int t = tid + k * NTHREADS;
            if (t < nv) {
                float4 v = __ldcs(xg + t);
                int s = t / 12;
                int j = (t % 12) * 4;
                float* dst = &sx[s * RSTRIDE + j];
                dst[0] = v.x; dst[1] = v.y; dst[2] = v.z; dst[3] = v.w;
            }
        }
    }
    __syncthreads();

    long long i = blockBase + tid;
    if (i >= nbatch) return;

    // ---- load rho (coalesced float4) ----
    float4 rr = __ldcs((const float4*)rho_real + i);
    float4 ri = __ldcs((const float4*)rho_imag + i);

    // ---- Pauli decomposition ----
    float t0r = 0.5f * (rr.x + rr.w), t0i = 0.5f * (ri.x + ri.w);
    float vzr = 0.5f * (rr.x - rr.w), vzi = 0.5f * (ri.x - ri.w);
    float vxr = 0.5f * (rr.y + rr.z), vxi = 0.5f * (ri.y + ri.z);
    float vyr = 0.5f * (ri.z - ri.y), vyi = 0.5f * (rr.y - rr.z);

    // ---- rotation chain, phi on the fly ----
    const float* xr = &sx[tid * RSTRIDE];
#define PHI(j) fmaf(xr[(j)], s_w[(j)], s_t[(j)])

    float zacc = 0.0f;
#pragma unroll
    for (int k = 0; k < 16; ++k) {
        float zang = -(zacc + PHI(3 * k + 2));
        float sz, cz;
        __sincosf(zang, &sz, &cz);
        {   // Rz: x' = c x - s y ; y' = s x + c y
            float nxr = cz * vxr - sz * vyr;
            float nyr = sz * vxr + cz * vyr;
            float nxi = cz * vxi - sz * vyi;
            float nyi = sz * vxi + cz * vyi;
            vxr = nxr; vyr = nyr; vxi = nxi; vyi = nyi;
        }
        float sy, cy;
        __sincosf(PHI(3 * k), &sy, &cy);
        {   // Ry: x' = c x + s z ; z' = -s x + c z
            float nxr = cy * vxr + sy * vzr;
            float nzr = -sy * vxr + cy * vzr;
            float nxi = cy * vxi + sy * vzi;
            float nzi = -sy * vxi + cy * vzi;
            vxr = nxr; vzr = nzr; vxi = nxi; vzi = nzi;
        }
        zacc = PHI(3 * k + 1);
    }
    {   // final Rz(-zacc)
        float sz, cz;
        __sincosf(-zacc, &sz, &cz);
        float nxr = cz * vxr - sz * vyr;
        float nyr = sz * vxr + cz * vyr;
        float nxi = cz * vxi - sz * vyi;
        float nyi = sz * vxi + cz * vyi;
        vxr = nxr; vyr = nyr; vxi = nxi; vyi = nyi;
    }
#undef PHI

    // ---- reconstruct rho' ----
    // r00=t0+tz, r01=tx-i ty, r10=tx+i ty, r11=t0-tz
    if (full_complex) {
        long long base = i * 8;
        if (base + 7 < out_elems) {
            float4* op = (float4*)(out + base);
            __stcs(op + 0, make_float4(t0r + vzr, t0i + vzi, vxr + vyi, vxi - vyr));
            __stcs(op + 1, make_float4(vxr - vyi, vxi + vyr, t0r - vzr, t0i - vzi));
        }
    } else {
        long long base = i * 4;
        if (base + 3 < out_elems) {
            __stcs((float4*)(out + base),
                   make_float4(t0r + vzr, vxr + vyi, vxr - vyi, t0r - vzr));
        }
    }
}

// ---- scalar fallback (any alignment) ---------------------------------------
__global__ void __launch_bounds__(NTHREADS) qlayer_kernel_scalar(
    const float* __restrict__ rho_real,
    const float* __restrict__ rho_imag,
    const float* __restrict__ x,
    const float* __restrict__ w,
    const float* __restrict__ theta,
    float* __restrict__ out,
    long long nbatch,
    long long out_elems,
    int full_complex)
{
    __shared__ float s_w[48];
    __shared__ float s_t[48];
    int tid = threadIdx.x;
    if (tid < 48) {
        s_w[tid] = w[tid];
        s_t[tid] = theta[tid];
    }
    __syncthreads();

    long long i = (long long)blockIdx.x * NTHREADS + tid;
    if (i >= nbatch) return;

    const float* xr = x + i * 48;
#define PHI(j) fmaf(xr[(j)], s_w[(j)], s_t[(j)])

    const float* rrp = rho_real + i * 4;
    const float* rip = rho_imag + i * 4;
    float rr0 = rrp[0], rr1 = rrp[1], rr2 = rrp[2], rr3 = rrp[3];
    float ri0 = rip[0], ri1 = rip[1], ri2 = rip[2], ri3 = rip[3];

    float t0r = 0.5f * (rr0 + rr3), t0i = 0.5f * (ri0 + ri3);
    float vzr = 0.5f * (rr0 - rr3), vzi = 0.5f * (ri0 - ri3);
    float vxr = 0.5f * (rr1 + rr2), vxi = 0.5f * (ri1 + ri2);
    float vyr = 0.5f * (ri2 - ri1), vyi = 0.5f * (rr1 - rr2);

    float zacc = 0.0f;
#pragma unroll
    for (int k = 0; k < 16; ++k) {
        float zang = -(zacc + PHI(3 * k + 2));
        float sz, cz;
        __sincosf(zang, &sz, &cz);
        {
            float nxr = cz * vxr - sz * vyr;
            float nyr = sz * vxr + cz * vyr;
            float nxi = cz * vxi - sz * vyi;
            float nyi = sz * vxi + cz * vyi;
            vxr = nxr; vyr = nyr; vxi = nxi; vyi = nyi;
        }
        float sy, cy;
        __sincosf(PHI(3 * k), &sy, &cy);
        {
            float nxr = cy * vxr + sy * vzr;
            float nzr = -sy * vxr + cy * vzr;
            float nxi = cy * vxi + sy * vzi;
            float nzi = -sy * vxi + cy * vzi;
            vxr = nxr; vzr = nzr; vxi = nxi; vzi = nzi;
        }
        zacc = PHI(3 * k + 1);
    }
    {
        float sz, cz;
        __sincosf(-zacc, &sz, &cz);
        float nxr = cz * vxr - sz * vyr;
        float nyr = sz * vxr + cz * vyr;
        float nxi = cz * vxi - sz * vyi;
        float nyi = sz * vxi + cz * vyi;
        vxr = nxr; vyr = nyr; vxi = nxi; vyi = nyi;
    }
#undef PHI

    if (full_complex) {
        long long base = i * 8;
        if (base + 7 < out_elems) {
            out[base + 0] = t0r + vzr; out[base + 1] = t0i + vzi;
            out[base + 2] = vxr + vyi; out[base + 3] = vxi - vyr;
            out[base + 4] = vxr - vyi; out[base + 5] = vxi + vyr;
            out[base + 6] = t0r - vzr; out[base + 7] = t0i - vzi;
        }
    } else {
        long long base = i * 4;
        if (base + 3 < out_elems) {
            out[base + 0] = t0r + vzr;
            out[base + 1] = vxr + vyi;
            out[base + 2] = vxr - vyi;
            out[base + 3] = t0r - vzr;
        }
    }
}

extern "C" void kernel_launch(void* const* d_in, const int* in_sizes, int n_in,
                              void* d_out, int out_size)
{
    const float* rho_real = nullptr;
    const float* rho_imag = nullptr;
    const float* x = nullptr;
    const float* w = nullptr;
    const float* theta = nullptr;
    long long B = 0;

    // 1) Strict metadata order (rho_real, rho_imag, x, w, theta).
    if (n_in >= 5) {
        long long s0 = in_sizes[0], s1 = in_sizes[1], s2 = in_sizes[2];
        long long s3 = in_sizes[3], s4 = in_sizes[4];
        if (s0 == s1 && s0 > 0 && (s0 % 4) == 0 &&
            s2 == 12 * s0 && s3 == 48 && s4 == 48) {
            rho_real = (const float*)d_in[0];
            rho_imag = (const float*)d_in[1];
            x        = (const float*)d_in[2];
            w        = (const float*)d_in[3];
            theta    = (const float*)d_in[4];
            B = s0 / 4;
        }
    }

    // 2) Fallback: consistency search over sizes.
    if (B == 0) {
        for (int a = 0; a < n_in && B == 0; ++a) {
            for (int b = a + 1; b < n_in && B == 0; ++b) {
                long long sa = in_sizes[a], sb = in_sizes[b];
                if (sa != sb || sa <= 0 || (sa % 4) != 0) continue;
                long long Bc = sa / 4;
                if (Bc < 2) continue;
                int xk = -1;
                for (int c = 0; c < n_in; ++c) {
                    if (c == a || c == b) continue;
                    if ((long long)in_sizes[c] == 48LL * Bc) { xk = c; break; }
                }
                if (xk < 0) continue;
                int s1i = -1, s2i = -1;
                for (int c = 0; c < n_in; ++c) {
                    if (c == a || c == b || c == xk) continue;
                    if (in_sizes[c] == 48) {
                        if (s1i < 0) s1i = c;
                        else if (s2i < 0) { s2i = c; break; }
                    }
                }
                if (s1i < 0 || s2i < 0) continue;
                rho_real = (const float*)d_in[a];
                rho_imag = (const float*)d_in[b];
                x        = (const float*)d_in[xk];
                w        = (const float*)d_in[s1i];
                theta    = (const float*)d_in[s2i];
                B = Bc;
            }
        }
    }

    float* out = (float*)d_out;
    long long out_elems = (long long)out_size;
    int full_complex = (B > 0 && out_elems >= 8 * B) ? 1 : 0;

    bool aligned =
        (((uintptr_t)x        & 15) == 0) &&
        (((uintptr_t)rho_real & 15) == 0) &&
        (((uintptr_t)rho_imag & 15) == 0) &&
        (((uintptr_t)out      & 15) == 0);

    unsigned nblk = (unsigned)(B > 0 ? (B + NTHREADS - 1) / NTHREADS : 1);
    if (B > 0 && aligned) {
        qlayer_kernel_vec<<<nblk, NTHREADS>>>(rho_real, rho_imag, x, w, theta, out,
                                              B, out_elems, full_complex);
    } else {
        qlayer_kernel_scalar<<<nblk, NTHREADS>>>(rho_real, rho_imag, x, w, theta, out,
                                                 B, out_elems, full_complex);
    }
}